// round 15
// baseline (speedup 1.0000x reference)
#include <cuda_runtime.h>
#include <cuda_bf16.h>
#include <cuda_fp16.h>
#include <math.h>
#include <stdint.h>

// ---------------- problem constants ----------------
#define LAYERS 6
#define BATCH  2
#define SEQ    1024
#define DMODEL 1024
#define NHEAD  16
#define HDIM   64
#define DFF    4096
#define WIN    5
#define TOKENS (BATCH*SEQ)          // 2048
#define EPS    1e-5f

// fp16 weight scratch layout (elements)
#define QKV_ELEMS  (LAYERS*DMODEL*3*DMODEL)
#define WO_ELEMS   (LAYERS*DMODEL*DMODEL)
#define W1_ELEMS   (LAYERS*DMODEL*DFF)
#define W2_ELEMS   (LAYERS*DFF*DMODEL)
#define WF_QKV 0
#define WF_WO  (QKV_ELEMS)
#define WF_W1  (WF_WO + WO_ELEMS)
#define WF_W2  (WF_W1 + W1_ELEMS)
#define WF_TOT (WF_W2 + W2_ELEMS)

// ---------------- device scratch (no allocation allowed) ----------------
__device__ float d_h   [TOKENS*DMODEL];
__device__ __half d_hnf [TOKENS*DMODEL];
__device__ __half d_qkvf[TOKENS*3*DMODEL];
__device__ __half d_of  [TOKENS*DMODEL];
__device__ __half d_fff [TOKENS*DFF];
__device__ __half d_wf16[WF_TOT];

// ---------------- small helpers ----------------
__device__ __forceinline__ float warp_sum(float v){
    #pragma unroll
    for (int o = 16; o; o >>= 1) v += __shfl_xor_sync(0xffffffffu, v, o);
    return v;
}
__device__ __forceinline__ float gelu_exact(float x){
    return 0.5f * x * (1.0f + erff(x * 0.70710678118654752440f));
}
__device__ __forceinline__ uint32_t smem_u32(const void* p){
    uint32_t a;
    asm("{ .reg .u64 t; cvta.to.shared.u64 t, %1; cvt.u32.u64 %0, t; }" : "=r"(a) : "l"(p));
    return a;
}
__device__ __forceinline__ uint32_t pack_f16_2(float x, float y){
    __half2 h = __floats2half2_rn(x, y);
    return *reinterpret_cast<uint32_t*>(&h);
}

// ---------------- mma.sync / ldmatrix / cp.async wrappers ----------------
__device__ __forceinline__ void mma_f16(float* d, const uint32_t* a, const uint32_t* b){
    asm volatile(
      "mma.sync.aligned.m16n8k16.row.col.f32.f16.f16.f32 "
      "{%0,%1,%2,%3}, {%4,%5,%6,%7}, {%8,%9}, {%0,%1,%2,%3};\n"
      : "+f"(d[0]), "+f"(d[1]), "+f"(d[2]), "+f"(d[3])
      : "r"(a[0]), "r"(a[1]), "r"(a[2]), "r"(a[3]), "r"(b[0]), "r"(b[1]));
}
__device__ __forceinline__ void ldsm_x4(uint32_t* r, uint32_t addr){
    asm volatile("ldmatrix.sync.aligned.m8n8.x4.shared.b16 {%0,%1,%2,%3}, [%4];"
      : "=r"(r[0]), "=r"(r[1]), "=r"(r[2]), "=r"(r[3]) : "r"(addr));
}
__device__ __forceinline__ void ldsm_x2(uint32_t* r, uint32_t addr){
    asm volatile("ldmatrix.sync.aligned.m8n8.x2.shared.b16 {%0,%1}, [%2];"
      : "=r"(r[0]), "=r"(r[1]) : "r"(addr));
}
__device__ __forceinline__ void ldsm_x2t(uint32_t* r, uint32_t addr){
    asm volatile("ldmatrix.sync.aligned.m8n8.x2.trans.shared.b16 {%0,%1}, [%2];"
      : "=r"(r[0]), "=r"(r[1]) : "r"(addr));
}
__device__ __forceinline__ void cp16(uint32_t s, const void* g){
    asm volatile("cp.async.cg.shared.global [%0], [%1], 16;\n" :: "r"(s), "l"(g));
}

// ---------------- fp16 GEMM smem layouts (KC=64, 3 stages) ----------------
#define KC       64
#define A_STRIDE 144
#define B_STRIDE 272
// 128x128 tile
#define F_B_OFF  18432
#define F_STAGE  35840
#define FGEMM_SMEM (3*F_STAGE)
// 64x128 tile
#define G_B_OFF  9216
#define G_STAGE  26624
#define GGEMM_SMEM (3*G_STAGE)

__device__ __forceinline__ void issue_stage_f16(
    const __half* __restrict__ A, const __half* __restrict__ B,
    uint32_t sb0, int tid, int m0, int n0, int K, int N, int c)
{
    uint32_t sb = sb0 + (uint32_t)(c % 3) * F_STAGE;
    int k0 = c * KC;
    #pragma unroll
    for (int i = 0; i < 4; i++){
        int idx = tid + i*256;
        int r = idx >> 3, cc = idx & 7;
        cp16(sb + r*A_STRIDE + cc*16, A + (size_t)(m0 + r) * K + k0 + cc*8);
    }
    #pragma unroll
    for (int i = 0; i < 4; i++){
        int idx = tid + i*256;
        int r = idx >> 4, cc = idx & 15;
        cp16(sb + F_B_OFF + r*B_STRIDE + cc*16, B + (size_t)(k0 + r) * N + n0 + cc*8);
    }
    asm volatile("cp.async.commit_group;");
}

__device__ __forceinline__ void issue_stage_g16(
    const __half* __restrict__ A, const __half* __restrict__ B,
    uint32_t sb0, int tid, int m0, int n0, int K, int N, int c)
{
    uint32_t sb = sb0 + (uint32_t)(c % 3) * G_STAGE;
    int k0 = c * KC;
    #pragma unroll
    for (int i = 0; i < 2; i++){
        int idx = tid + i*256;
        int r = idx >> 3, cc = idx & 7;
        cp16(sb + r*A_STRIDE + cc*16, A + (size_t)(m0 + r) * K + k0 + cc*8);
    }
    #pragma unroll
    for (int i = 0; i < 4; i++){
        int idx = tid + i*256;
        int r = idx >> 4, cc = idx & 15;
        cp16(sb + G_B_OFF + r*B_STRIDE + cc*16, B + (size_t)(k0 + r) * N + n0 + cc*8);
    }
    asm volatile("cp.async.commit_group;");
}

// =====================================================================
// fp16 1-pass GEMM, 128x128 tile: C = epi(A @ B + bias)
// EPI: 0 = bias -> fp16   1 = bias+residual (f32)   2 = bias+GELU -> fp16
// =====================================================================
template<int EPI>
__global__ __launch_bounds__(256, 2)
void gemm_f16(const __half* __restrict__ A, const __half* __restrict__ B,
              const float* __restrict__ bias, const float* __restrict__ res,
              float* __restrict__ C, __half* __restrict__ Cf,
              int M, int N, int K)
{
    extern __shared__ char smem[];
    const uint32_t sb0 = smem_u32(smem);
    const int tid  = threadIdx.x;
    const int lane = tid & 31, wid = tid >> 5;
    const int m0 = blockIdx.y * 128, n0 = blockIdx.x * 128;
    const int wm = (wid >> 2) * 64, wn = (wid & 3) * 32;

    float acc[4][4][4];
    #pragma unroll
    for (int a = 0; a < 4; a++)
        #pragma unroll
        for (int b = 0; b < 4; b++)
            #pragma unroll
            for (int cc = 0; cc < 4; cc++) acc[a][b][cc] = 0.f;

    const int nch = K / KC;
    issue_stage_f16(A, B, sb0, tid, m0, n0, K, N, 0);
    issue_stage_f16(A, B, sb0, tid, m0, n0, K, N, 1);

    const uint32_t a_lrow = wm + (lane & 15);
    const uint32_t a_lcol = (lane >> 4) * 8;
    const uint32_t b_lrow = (lane & 15);

    for (int c = 0; c < nch; c++){
        asm volatile("cp.async.wait_group %0;" :: "n"(1));
        __syncthreads();
        if (c + 2 < nch) issue_stage_f16(A, B, sb0, tid, m0, n0, K, N, c + 2);
        else asm volatile("cp.async.commit_group;");

        uint32_t sb = sb0 + (uint32_t)(c % 3) * F_STAGE;
        #pragma unroll
        for (int ks = 0; ks < 4; ks++){
            uint32_t ah[4][4], bb[4][2];
            #pragma unroll
            for (int mt = 0; mt < 4; mt++)
                ldsm_x4(ah[mt], sb + (a_lrow + mt*16)*A_STRIDE + (ks*16 + a_lcol)*2);
            #pragma unroll
            for (int nt = 0; nt < 4; nt++)
                ldsm_x2t(bb[nt], sb + F_B_OFF + (ks*16 + b_lrow)*B_STRIDE + (wn + nt*8)*2);
            #pragma unroll
            for (int mt = 0; mt < 4; mt++)
                #pragma unroll
                for (int nt = 0; nt < 4; nt++)
                    mma_f16(acc[mt][nt], ah[mt], bb[nt]);
        }
    }

    const int g  = lane >> 2;
    const int tq = (lane & 3) * 2;
    #pragma unroll
    for (int mt = 0; mt < 4; mt++){
        #pragma unroll
        for (int half = 0; half < 2; half++){
            int m = m0 + wm + mt*16 + g + half*8;
            #pragma unroll
            for (int nt = 0; nt < 4; nt++){
                int n = n0 + wn + nt*8 + tq;
                float v0 = acc[mt][nt][half*2+0] + bias[n];
                float v1 = acc[mt][nt][half*2+1] + bias[n+1];
                size_t gi = (size_t)m * N + n;
                if (EPI == 1){
                    v0 += res[gi]; v1 += res[gi+1];
                    float2 o; o.x = v0; o.y = v1;
                    *(float2*)&C[gi] = o;
                } else {
                    if (EPI == 2){ v0 = gelu_exact(v0); v1 = gelu_exact(v1); }
                    *(uint32_t*)&Cf[gi] = pack_f16_2(v0, v1);
                }
            }
        }
    }
}

// =====================================================================
// fp16 1-pass GEMM, 64x128 tile: bias + residual, f32 out.
// =====================================================================
__global__ __launch_bounds__(256, 2)
void gemm_g16(const __half* __restrict__ A, const __half* __restrict__ B,
              const float* __restrict__ bias, const float* __restrict__ res,
              float* __restrict__ C, int M, int N, int K)
{
    extern __shared__ char smem[];
    const uint32_t sb0 = smem_u32(smem);
    const int tid  = threadIdx.x;
    const int lane = tid & 31, wid = tid >> 5;
    const int m0 = blockIdx.y * 64, n0 = blockIdx.x * 128;
    const int wm = (wid >> 2) * 32, wn = (wid & 3) * 32;

    float acc[2][4][4];
    #pragma unroll
    for (int a = 0; a < 2; a++)
        #pragma unroll
        for (int b = 0; b < 4; b++)
            #pragma unroll
            for (int cc = 0; cc < 4; cc++) acc[a][b][cc] = 0.f;

    const int nch = K / KC;
    issue_stage_g16(A, B, sb0, tid, m0, n0, K, N, 0);
    issue_stage_g16(A, B, sb0, tid, m0, n0, K, N, 1);

    const uint32_t a_lrow = wm + (lane & 15);
    const uint32_t a_lcol = (lane >> 4) * 8;
    const uint32_t b_lrow = (lane & 15);

    for (int c = 0; c < nch; c++){
        asm volatile("cp.async.wait_group %0;" :: "n"(1));
        __syncthreads();
        if (c + 2 < nch) issue_stage_g16(A, B, sb0, tid, m0, n0, K, N, c + 2);
        else asm volatile("cp.async.commit_group;");

        uint32_t sb = sb0 + (uint32_t)(c % 3) * G_STAGE;
        #pragma unroll
        for (int ks = 0; ks < 4; ks++){
            uint32_t ah[2][4], bb[4][2];
            #pragma unroll
            for (int mt = 0; mt < 2; mt++)
                ldsm_x4(ah[mt], sb + (a_lrow + mt*16)*A_STRIDE + (ks*16 + a_lcol)*2);
            #pragma unroll
            for (int nt = 0; nt < 4; nt++)
                ldsm_x2t(bb[nt], sb + G_B_OFF + (ks*16 + b_lrow)*B_STRIDE + (wn + nt*8)*2);
            #pragma unroll
            for (int mt = 0; mt < 2; mt++)
                #pragma unroll
                for (int nt = 0; nt < 4; nt++)
                    mma_f16(acc[mt][nt], ah[mt], bb[nt]);
        }
    }

    const int g  = lane >> 2;
    const int tq = (lane & 3) * 2;
    #pragma unroll
    for (int mt = 0; mt < 2; mt++){
        #pragma unroll
        for (int half = 0; half < 2; half++){
            int m = m0 + wm + mt*16 + g + half*8;
            #pragma unroll
            for (int nt = 0; nt < 4; nt++){
                int n = n0 + wn + nt*8 + tq;
                float v0 = acc[mt][nt][half*2+0] + bias[n];
                float v1 = acc[mt][nt][half*2+1] + bias[n+1];
                size_t gi = (size_t)m * N + n;
                v0 += res[gi]; v1 += res[gi+1];
                float2 o; o.x = v0; o.y = v1;
                *(float2*)&C[gi] = o;
            }
        }
    }
}

// =====================================================================
// Flash attention, single fp16, causal. One 64-row q-tile per CTA,
// grid (32 bh, 16 q-tiles) = 512 CTAs, 4 warps x 16 rows, 4 CTAs/SM.
// smem: Q 0..9216 | stage s at 9216+s*18432: K +0, V +9216
// =====================================================================
#define FL_SMEM 46080

__global__ __launch_bounds__(128, 4)
void flash_kernel(const __half* __restrict__ qkvf, __half* __restrict__ of)
{
    extern __shared__ char fsm[];
    const uint32_t sb = smem_u32(fsm);
    const int tid = threadIdx.x, lane = tid & 31, w = tid >> 5;   // w 0..3
    const int bh = blockIdx.x;
    const int it = blockIdx.y;                                    // 0..15
    const int b = bh >> 4, h = bh & 15;
    const int nk = it + 1;
    const size_t rs = 3*DMODEL;

    #define ISSUE_KV(jt_) do {                                               \
        uint32_t st_ = sb + 9216u + (uint32_t)((jt_)&1)*18432u;              \
        const size_t tok0_ = (size_t)(b*SEQ + (jt_)*64);                     \
        _Pragma("unroll")                                                    \
        for (int i_ = 0; i_ < 4; i_++){                                      \
            int idx_ = tid + i_*128;                                         \
            int r_ = idx_ >> 3, c_ = idx_ & 7;                               \
            uint32_t sa_ = st_ + r_*144 + c_*16;                             \
            cp16(sa_,        qkvf + (tok0_ + r_)*rs + DMODEL   + h*64 + c_*8); \
            cp16(sa_ + 9216, qkvf + (tok0_ + r_)*rs + 2*DMODEL + h*64 + c_*8); \
        }                                                                    \
        asm volatile("cp.async.commit_group;");                              \
    } while(0)

    // ---- Q loads (own group) ----
    {
        const size_t tok0 = (size_t)(b*SEQ + it*64);
        #pragma unroll
        for (int i = 0; i < 4; i++){
            int idx = tid + i*128;
            int r = idx >> 3, c = idx & 7;
            cp16(sb + r*144 + c*16, qkvf + (tok0 + r)*rs + h*64 + c*8);
        }
        asm volatile("cp.async.commit_group;");
    }
    ISSUE_KV(0);
    asm volatile("cp.async.wait_group 1;");   // Q ready
    __syncthreads();

    uint32_t qh[4][4];
    {
        uint32_t rbase = sb + (w*16 + (lane & 15))*144 + ((lane >> 4)*8)*2;
        #pragma unroll
        for (int ks = 0; ks < 4; ks++)
            ldsm_x4(qh[ks], rbase + ks*32);
    }

    float O[8][4];
    #pragma unroll
    for (int nt = 0; nt < 8; nt++)
        #pragma unroll
        for (int c = 0; c < 4; c++) O[nt][c] = 0.f;
    float m0 = -INFINITY, m1 = -INFINITY, l0 = 0.f, l1 = 0.f;
    const int r0g = it*64 + w*16 + (lane >> 2);

    for (int jt = 0; jt < nk; jt++){
        if (jt + 1 < nk){ ISSUE_KV(jt+1); asm volatile("cp.async.wait_group 1;"); }
        else            { asm volatile("cp.async.wait_group 0;"); }
        __syncthreads();
        const uint32_t st = sb + 9216u + (uint32_t)(jt&1)*18432u;

        float S[8][4];
        #pragma unroll
        for (int nt = 0; nt < 8; nt++)
            #pragma unroll
            for (int c = 0; c < 4; c++) S[nt][c] = 0.f;

        const uint32_t kb = st + (lane & 7)*144 + (((lane >> 3) & 1)*8)*2;
        #pragma unroll
        for (int nt = 0; nt < 8; nt++){
            #pragma unroll
            for (int ks = 0; ks < 4; ks++){
                uint32_t kh[2];
                ldsm_x2(kh, kb + nt*8*144 + ks*32);
                mma_f16(S[nt], qh[ks], kh);
            }
        }

        const bool diag = (jt == it);
        float mx0 = -INFINITY, mx1 = -INFINITY;
        #pragma unroll
        for (int nt = 0; nt < 8; nt++){
            int colb = jt*64 + nt*8 + (lane & 3)*2;
            #pragma unroll
            for (int q = 0; q < 2; q++){
                float v0 = S[nt][q]   * 0.125f;
                float v1 = S[nt][2+q] * 0.125f;
                if (diag){
                    if (colb + q > r0g)     v0 = -INFINITY;
                    if (colb + q > r0g + 8) v1 = -INFINITY;
                }
                S[nt][q] = v0; S[nt][2+q] = v1;
                mx0 = fmaxf(mx0, v0); mx1 = fmaxf(mx1, v1);
            }
        }
        mx0 = fmaxf(mx0, __shfl_xor_sync(0xffffffffu, mx0, 1));
        mx0 = fmaxf(mx0, __shfl_xor_sync(0xffffffffu, mx0, 2));
        mx1 = fmaxf(mx1, __shfl_xor_sync(0xffffffffu, mx1, 1));
        mx1 = fmaxf(mx1, __shfl_xor_sync(0xffffffffu, mx1, 2));
        float mn0 = fmaxf(m0, mx0), mn1 = fmaxf(m1, mx1);
        float f0 = __expf(m0 - mn0), f1 = __expf(m1 - mn1);
        m0 = mn0; m1 = mn1;
        float ls0 = 0.f, ls1 = 0.f;
        #pragma unroll
        for (int nt = 0; nt < 8; nt++){
            #pragma unroll
            for (int q = 0; q < 2; q++){
                float e0 = __expf(S[nt][q]   - m0);
                float e1 = __expf(S[nt][2+q] - m1);
                S[nt][q] = e0; S[nt][2+q] = e1;
                ls0 += e0; ls1 += e1;
            }
        }
        l0 = l0*f0 + ls0;
        l1 = l1*f1 + ls1;
        #pragma unroll
        for (int nt = 0; nt < 8; nt++){
            O[nt][0] *= f0; O[nt][1] *= f0;
            O[nt][2] *= f1; O[nt][3] *= f1;
        }

        #pragma unroll
        for (int ks = 0; ks < 4; ks++){
            uint32_t ph[4];
            ph[0] = pack_f16_2(S[2*ks][0],   S[2*ks][1]);
            ph[1] = pack_f16_2(S[2*ks][2],   S[2*ks][3]);
            ph[2] = pack_f16_2(S[2*ks+1][0], S[2*ks+1][1]);
            ph[3] = pack_f16_2(S[2*ks+1][2], S[2*ks+1][3]);
            uint32_t vb = st + 9216u + (ks*16 + (lane & 15))*144;
            #pragma unroll
            for (int nt = 0; nt < 8; nt++){
                uint32_t vh[2];
                ldsm_x2t(vh, vb + nt*16);
                mma_f16(O[nt], ph, vh);
            }
        }
        __syncthreads();
    }

    l0 += __shfl_xor_sync(0xffffffffu, l0, 1);
    l0 += __shfl_xor_sync(0xffffffffu, l0, 2);
    l1 += __shfl_xor_sync(0xffffffffu, l1, 1);
    l1 += __shfl_xor_sync(0xffffffffu, l1, 2);
    float inv0 = 1.0f / l0, inv1 = 1.0f / l1;
    const size_t tok0 = (size_t)(b*SEQ + it*64 + w*16 + (lane >> 2));
    const int colb = h*64 + (lane & 3)*2;
    #pragma unroll
    for (int nt = 0; nt < 8; nt++){
        #pragma unroll
        for (int rh = 0; rh < 2; rh++){
            float inv = rh ? inv1 : inv0;
            float v0 = O[nt][rh*2+0] * inv;
            float v1 = O[nt][rh*2+1] * inv;
            size_t gi = (tok0 + rh*8)*DMODEL + colb + nt*8;
            *(uint32_t*)&of[gi] = pack_f16_2(v0, v1);
        }
    }
    #undef ISSUE_KV
}

// ---------------- merged weight convert: fp32 -> fp16 (all 4 tensors) ----------------
__global__ void wconv_all_kernel(const float4* __restrict__ Wqkv,
                                 const float4* __restrict__ Wo,
                                 const float4* __restrict__ W1,
                                 const float4* __restrict__ W2,
                                 uint2* __restrict__ out){
    int i = blockIdx.x * blockDim.x + threadIdx.x;
    if (i >= WF_TOT/4) return;
    const float4* src;
    int off;
    if (i < WF_WO/4){ src = Wqkv; off = i; }
    else if (i < WF_W1/4){ src = Wo; off = i - WF_WO/4; }
    else if (i < WF_W2/4){ src = W1; off = i - WF_W1/4; }
    else { src = W2; off = i - WF_W2/4; }
    float4 v = src[off];
    uint2 o;
    o.x = pack_f16_2(v.x, v.y);
    o.y = pack_f16_2(v.z, v.w);
    out[i] = o;
}

// ---------------- LayerNorm: single fp16 out ----------------
__global__ void ln_kernel(const float* __restrict__ in,
                          const float* __restrict__ w,
                          const float* __restrict__ b,
                          __half* __restrict__ outf){
    int row = blockIdx.x;
    int t   = threadIdx.x;
    const float* x = in + (size_t)row * DMODEL;
    float4 v = *(const float4*)&x[t*4];
    float s  = v.x + v.y + v.z + v.w;
    float sq = v.x*v.x + v.y*v.y + v.z*v.z + v.w*v.w;
    s  = warp_sum(s);
    sq = warp_sum(sq);
    __shared__ float sh1[8], sh2[8];
    int warp = t >> 5, lane = t & 31;
    if (lane == 0){ sh1[warp] = s; sh2[warp] = sq; }
    __syncthreads();
    float tot = 0.f, tot2 = 0.f;
    #pragma unroll
    for (int i = 0; i < 8; i++){ tot += sh1[i]; tot2 += sh2[i]; }
    float mu   = tot  * (1.0f/DMODEL);
    float var  = tot2 * (1.0f/DMODEL) - mu*mu;
    float rstd = rsqrtf(var + EPS);
    float4 wv = *(const float4*)&w[t*4];
    float4 bv = *(const float4*)&b[t*4];
    float4 ov;
    ov.x = (v.x - mu)*rstd*wv.x + bv.x;
    ov.y = (v.y - mu)*rstd*wv.y + bv.y;
    ov.z = (v.z - mu)*rstd*wv.z + bv.z;
    ov.w = (v.w - mu)*rstd*wv.w + bv.w;
    size_t base = (size_t)row*DMODEL + t*4;
    uint2 H;
    H.x = pack_f16_2(ov.x, ov.y);
    H.y = pack_f16_2(ov.z, ov.w);
    *(uint2*)&outf[base] = H;
}

// ---------------- fused final LayerNorm + projection ----------------
__global__ __launch_bounds__(256)
void lnpred_kernel(const float* __restrict__ in,
                   const float* __restrict__ w,
                   const float* __restrict__ b,
                   const float* __restrict__ Wp,
                   const float* __restrict__ bp,
                   float* __restrict__ out){
    int row = blockIdx.x;
    int t   = threadIdx.x;
    const float* x = in + (size_t)row * DMODEL;
    float4 v = *(const float4*)&x[t*4];
    float s  = v.x + v.y + v.z + v.w;
    float sq = v.x*v.x + v.y*v.y + v.z*v.z + v.w*v.w;
    s  = warp_sum(s);
    sq = warp_sum(sq);
    __shared__ float sh1[8], sh2[8];
    int warp = t >> 5, lane = t & 31;
    if (lane == 0){ sh1[warp] = s; sh2[warp] = sq; }
    __syncthreads();
    float tot = 0.f, tot2 = 0.f;
    #pragma unroll
    for (int i = 0; i < 8; i++){ tot += sh1[i]; tot2 += sh2[i]; }
    float mu   = tot  * (1.0f/DMODEL);
    float var  = tot2 * (1.0f/DMODEL) - mu*mu;
    float rstd = rsqrtf(var + EPS);
    float4 wv = *(const float4*)&w[t*4];
    float4 bv = *(const float4*)&b[t*4];
    float4 ov;
    ov.x = (v.x - mu)*rstd*wv.x + bv.x;
    ov.y = (v.y - mu)*rstd*wv.y + bv.y;
    ov.z = (v.z - mu)*rstd*wv.z + bv.z;
    ov.w = (v.w - mu)*rstd*wv.w + bv.w;

    float local[WIN];
    {
        const float* w0 = Wp + (size_t)(t*4) * WIN;
        #pragma unroll
        for (int p = 0; p < WIN; p++)
            local[p] = ov.x*w0[p] + ov.y*w0[WIN+p] + ov.z*w0[2*WIN+p] + ov.w*w0[3*WIN+p];
    }
    __shared__ float red[WIN][256];
    #pragma unroll
    for (int p = 0; p < WIN; p++) red[p][t] = local[p];
    __syncthreads();
    for (int sHalf = 128; sHalf > 0; sHalf >>= 1){
        if (t < sHalf){
            #pragma unroll
            for (int p = 0; p < WIN; p++) red[p][t] += red[p][t + sHalf];
        }
        __syncthreads();
    }
    if (t < WIN) out[(size_t)row * WIN + t] = red[t][0] + bp[t];
}

// ---------------- host orchestration ----------------
extern "C" void kernel_launch(void* const* d_in, const int* in_sizes, int n_in,
                              void* d_out, int out_size){
    const float* x     = (const float*)d_in[0];
    const float* Wqkv  = (const float*)d_in[1];
    const float* bqkv  = (const float*)d_in[2];
    const float* Wo    = (const float*)d_in[3];
    const float* bo    = (const float*)d_in[4];
    const float* ln1w  = (const float*)d_in[5];
    const float* ln1b  = (const float*)d_in[6];
    const float* W1    = (const float*)d_in[7];
    const float* b1    = (const float*)d_in[8];
    const float* W2    = (const float*)d_in[9];
    const float* b2    = (const float*)d_in[10];
    const float* ln2w  = (const float*)d_in[11];
    const float* ln2b  = (const float*)d_in[12];
    const float* lnfw  = (const float*)d_in[13];
    const float* lnfb  = (const float*)d_in[14];
    const float* Wp    = (const float*)d_in[15];
    const float* bp    = (const float*)d_in[16];
    float* out = (float*)d_out;

    float *g_h;
    __half *g_hnf, *g_qkvf, *g_of, *g_fff, *g_wf16;
    cudaGetSymbolAddress((void**)&g_h,    d_h);
    cudaGetSymbolAddress((void**)&g_hnf,  d_hnf);
    cudaGetSymbolAddress((void**)&g_qkvf, d_qkvf);
    cudaGetSymbolAddress((void**)&g_of,   d_of);
    cudaGetSymbolAddress((void**)&g_fff,  d_fff);
    cudaGetSymbolAddress((void**)&g_wf16, d_wf16);

    cudaFuncSetAttribute(gemm_f16<0>, cudaFuncAttributeMaxDynamicSharedMemorySize, FGEMM_SMEM);
    cudaFuncSetAttribute(gemm_f16<2>, cudaFuncAttributeMaxDynamicSharedMemorySize, FGEMM_SMEM);
    cudaFuncSetAttribute(gemm_g16,    cudaFuncAttributeMaxDynamicSharedMemorySize, GGEMM_SMEM);
    cudaFuncSetAttribute(flash_kernel, cudaFuncAttributeMaxDynamicSharedMemorySize, FL_SMEM);

    wconv_all_kernel<<<(WF_TOT/4 + 255)/256, 256>>>(
        (const float4*)Wqkv, (const float4*)Wo, (const float4*)W1, (const float4*)W2,
        (uint2*)g_wf16);

    for (int l = 0; l < LAYERS; l++){
        const __half* wqkv = g_wf16 + WF_QKV + (size_t)l * DMODEL * 3*DMODEL;
        const __half* wo   = g_wf16 + WF_WO  + (size_t)l * DMODEL * DMODEL;
        const __half* w1   = g_wf16 + WF_W1  + (size_t)l * DMODEL * DFF;
        const __half* w2   = g_wf16 + WF_W2  + (size_t)l * DFF * DMODEL;
        const float* bq = bqkv + (size_t)l * 3*DMODEL;
        const float* bO = bo   + (size_t)l * DMODEL;
        const float* B1 = b1   + (size_t)l * DFF;
        const float* B2 = b2   + (size_t)l * DMODEL;
        const float* hin = (l == 0) ? x : g_h;

        // pre-norm attention
        ln_kernel<<<TOKENS, 256>>>(hin, ln1w + l*DMODEL, ln1b + l*DMODEL, g_hnf);
        gemm_f16<0><<<dim3(3*DMODEL/128, TOKENS/128), 256, FGEMM_SMEM>>>(
            g_hnf, wqkv, bq, nullptr, nullptr, g_qkvf, TOKENS, 3*DMODEL, DMODEL);
        flash_kernel<<<dim3(BATCH*NHEAD, 16), 128, FL_SMEM>>>(g_qkvf, g_of);
        gemm_g16<<<dim3(DMODEL/128, TOKENS/64), 256, GGEMM_SMEM>>>(
            g_of, wo, bO, hin, g_h, TOKENS, DMODEL, DMODEL);

        // pre-norm FFN
        ln_kernel<<<TOKENS, 256>>>(g_h, ln2w + l*DMODEL, ln2b + l*DMODEL, g_hnf);
        gemm_f16<2><<<dim3(DFF/128, TOKENS/128), 256, FGEMM_SMEM>>>(
            g_hnf, w1, B1, nullptr, nullptr, g_fff, TOKENS, DFF, DMODEL);
        gemm_g16<<<dim3(DMODEL/128, TOKENS/64), 256, GGEMM_SMEM>>>(
            g_fff, w2, B2, g_h, g_h, TOKENS, DMODEL, DFF);
    }

    lnpred_kernel<<<TOKENS, 256>>>(g_h, lnfw, lnfb, Wp, bp, out);
    (void)in_sizes; (void)n_in; (void)out_size;
}

// round 16
// speedup vs baseline: 1.0247x; 1.0247x over previous
#include <cuda_runtime.h>
#include <cuda_bf16.h>
#include <cuda_fp16.h>
#include <math.h>
#include <stdint.h>

// ---------------- problem constants ----------------
#define LAYERS 6
#define BATCH  2
#define SEQ    1024
#define DMODEL 1024
#define NHEAD  16
#define HDIM   64
#define DFF    4096
#define WIN    5
#define TOKENS (BATCH*SEQ)          // 2048
#define EPS    1e-5f

// fp16 weight scratch layout (elements)
#define QKV_ELEMS  (LAYERS*DMODEL*3*DMODEL)
#define WO_ELEMS   (LAYERS*DMODEL*DMODEL)
#define W1_ELEMS   (LAYERS*DMODEL*DFF)
#define W2_ELEMS   (LAYERS*DFF*DMODEL)
#define WF_QKV 0
#define WF_WO  (QKV_ELEMS)
#define WF_W1  (WF_WO + WO_ELEMS)
#define WF_W2  (WF_W1 + W1_ELEMS)
#define WF_TOT (WF_W2 + W2_ELEMS)

// ---------------- device scratch (no allocation allowed) ----------------
__device__ float d_h   [TOKENS*DMODEL];
__device__ __half d_hnf [TOKENS*DMODEL];
__device__ __half d_qkvf[TOKENS*3*DMODEL];
__device__ __half d_of  [TOKENS*DMODEL];
__device__ __half d_fff [TOKENS*DFF];
__device__ __half d_wf16[WF_TOT];

// ---------------- small helpers ----------------
__device__ __forceinline__ float warp_sum(float v){
    #pragma unroll
    for (int o = 16; o; o >>= 1) v += __shfl_xor_sync(0xffffffffu, v, o);
    return v;
}
__device__ __forceinline__ float gelu_exact(float x){
    return 0.5f * x * (1.0f + erff(x * 0.70710678118654752440f));
}
__device__ __forceinline__ uint32_t smem_u32(const void* p){
    uint32_t a;
    asm("{ .reg .u64 t; cvta.to.shared.u64 t, %1; cvt.u32.u64 %0, t; }" : "=r"(a) : "l"(p));
    return a;
}
__device__ __forceinline__ uint32_t pack_f16_2(float x, float y){
    __half2 h = __floats2half2_rn(x, y);
    return *reinterpret_cast<uint32_t*>(&h);
}

// ---------------- mma.sync / ldmatrix / cp.async wrappers ----------------
__device__ __forceinline__ void mma_f16(float* d, const uint32_t* a, const uint32_t* b){
    asm volatile(
      "mma.sync.aligned.m16n8k16.row.col.f32.f16.f16.f32 "
      "{%0,%1,%2,%3}, {%4,%5,%6,%7}, {%8,%9}, {%0,%1,%2,%3};\n"
      : "+f"(d[0]), "+f"(d[1]), "+f"(d[2]), "+f"(d[3])
      : "r"(a[0]), "r"(a[1]), "r"(a[2]), "r"(a[3]), "r"(b[0]), "r"(b[1]));
}
__device__ __forceinline__ void ldsm_x4(uint32_t* r, uint32_t addr){
    asm volatile("ldmatrix.sync.aligned.m8n8.x4.shared.b16 {%0,%1,%2,%3}, [%4];"
      : "=r"(r[0]), "=r"(r[1]), "=r"(r[2]), "=r"(r[3]) : "r"(addr));
}
__device__ __forceinline__ void ldsm_x2(uint32_t* r, uint32_t addr){
    asm volatile("ldmatrix.sync.aligned.m8n8.x2.shared.b16 {%0,%1}, [%2];"
      : "=r"(r[0]), "=r"(r[1]) : "r"(addr));
}
__device__ __forceinline__ void ldsm_x2t(uint32_t* r, uint32_t addr){
    asm volatile("ldmatrix.sync.aligned.m8n8.x2.trans.shared.b16 {%0,%1}, [%2];"
      : "=r"(r[0]), "=r"(r[1]) : "r"(addr));
}
__device__ __forceinline__ void cp16(uint32_t s, const void* g){
    asm volatile("cp.async.cg.shared.global [%0], [%1], 16;\n" :: "r"(s), "l"(g));
}
// packed fp16x2 exp2 (approx) -- halves MUFU count in softmax
__device__ __forceinline__ uint32_t ex2_f16x2(uint32_t a){
    asm("ex2.approx.f16x2 %0, %0;" : "+r"(a));
    return a;
}

// ---------------- fp16 GEMM smem layouts (KC=64, 3 stages) ----------------
#define KC       64
#define A_STRIDE 144
#define B_STRIDE 272
// 128x128 tile
#define F_B_OFF  18432
#define F_STAGE  35840
#define FGEMM_SMEM (3*F_STAGE)
// 64x128 tile
#define G_B_OFF  9216
#define G_STAGE  26624
#define GGEMM_SMEM (3*G_STAGE)

__device__ __forceinline__ void issue_stage_f16(
    const __half* __restrict__ A, const __half* __restrict__ B,
    uint32_t sb0, int tid, int m0, int n0, int K, int N, int c)
{
    uint32_t sb = sb0 + (uint32_t)(c % 3) * F_STAGE;
    int k0 = c * KC;
    #pragma unroll
    for (int i = 0; i < 4; i++){
        int idx = tid + i*256;
        int r = idx >> 3, cc = idx & 7;
        cp16(sb + r*A_STRIDE + cc*16, A + (size_t)(m0 + r) * K + k0 + cc*8);
    }
    #pragma unroll
    for (int i = 0; i < 4; i++){
        int idx = tid + i*256;
        int r = idx >> 4, cc = idx & 15;
        cp16(sb + F_B_OFF + r*B_STRIDE + cc*16, B + (size_t)(k0 + r) * N + n0 + cc*8);
    }
    asm volatile("cp.async.commit_group;");
}

__device__ __forceinline__ void issue_stage_g16(
    const __half* __restrict__ A, const __half* __restrict__ B,
    uint32_t sb0, int tid, int m0, int n0, int K, int N, int c)
{
    uint32_t sb = sb0 + (uint32_t)(c % 3) * G_STAGE;
    int k0 = c * KC;
    #pragma unroll
    for (int i = 0; i < 2; i++){
        int idx = tid + i*256;
        int r = idx >> 3, cc = idx & 7;
        cp16(sb + r*A_STRIDE + cc*16, A + (size_t)(m0 + r) * K + k0 + cc*8);
    }
    #pragma unroll
    for (int i = 0; i < 4; i++){
        int idx = tid + i*256;
        int r = idx >> 4, cc = idx & 15;
        cp16(sb + G_B_OFF + r*B_STRIDE + cc*16, B + (size_t)(k0 + r) * N + n0 + cc*8);
    }
    asm volatile("cp.async.commit_group;");
}

// =====================================================================
// fp16 1-pass GEMM, 128x128 tile: C = epi(A @ B + bias)
// EPI: 0 = bias -> fp16   1 = bias+residual (f32)   2 = bias+GELU -> fp16
// =====================================================================
template<int EPI>
__global__ __launch_bounds__(256, 2)
void gemm_f16(const __half* __restrict__ A, const __half* __restrict__ B,
              const float* __restrict__ bias, const float* __restrict__ res,
              float* __restrict__ C, __half* __restrict__ Cf,
              int M, int N, int K)
{
    extern __shared__ char smem[];
    const uint32_t sb0 = smem_u32(smem);
    const int tid  = threadIdx.x;
    const int lane = tid & 31, wid = tid >> 5;
    const int m0 = blockIdx.y * 128, n0 = blockIdx.x * 128;
    const int wm = (wid >> 2) * 64, wn = (wid & 3) * 32;

    float acc[4][4][4];
    #pragma unroll
    for (int a = 0; a < 4; a++)
        #pragma unroll
        for (int b = 0; b < 4; b++)
            #pragma unroll
            for (int cc = 0; cc < 4; cc++) acc[a][b][cc] = 0.f;

    const int nch = K / KC;
    issue_stage_f16(A, B, sb0, tid, m0, n0, K, N, 0);
    issue_stage_f16(A, B, sb0, tid, m0, n0, K, N, 1);

    const uint32_t a_lrow = wm + (lane & 15);
    const uint32_t a_lcol = (lane >> 4) * 8;
    const uint32_t b_lrow = (lane & 15);

    for (int c = 0; c < nch; c++){
        asm volatile("cp.async.wait_group %0;" :: "n"(1));
        __syncthreads();
        if (c + 2 < nch) issue_stage_f16(A, B, sb0, tid, m0, n0, K, N, c + 2);
        else asm volatile("cp.async.commit_group;");

        uint32_t sb = sb0 + (uint32_t)(c % 3) * F_STAGE;
        #pragma unroll
        for (int ks = 0; ks < 4; ks++){
            uint32_t ah[4][4], bb[4][2];
            #pragma unroll
            for (int mt = 0; mt < 4; mt++)
                ldsm_x4(ah[mt], sb + (a_lrow + mt*16)*A_STRIDE + (ks*16 + a_lcol)*2);
            #pragma unroll
            for (int nt = 0; nt < 4; nt++)
                ldsm_x2t(bb[nt], sb + F_B_OFF + (ks*16 + b_lrow)*B_STRIDE + (wn + nt*8)*2);
            #pragma unroll
            for (int mt = 0; mt < 4; mt++)
                #pragma unroll
                for (int nt = 0; nt < 4; nt++)
                    mma_f16(acc[mt][nt], ah[mt], bb[nt]);
        }
    }

    const int g  = lane >> 2;
    const int tq = (lane & 3) * 2;
    #pragma unroll
    for (int mt = 0; mt < 4; mt++){
        #pragma unroll
        for (int half = 0; half < 2; half++){
            int m = m0 + wm + mt*16 + g + half*8;
            #pragma unroll
            for (int nt = 0; nt < 4; nt++){
                int n = n0 + wn + nt*8 + tq;
                float v0 = acc[mt][nt][half*2+0] + bias[n];
                float v1 = acc[mt][nt][half*2+1] + bias[n+1];
                size_t gi = (size_t)m * N + n;
                if (EPI == 1){
                    v0 += res[gi]; v1 += res[gi+1];
                    float2 o; o.x = v0; o.y = v1;
                    *(float2*)&C[gi] = o;
                } else {
                    if (EPI == 2){ v0 = gelu_exact(v0); v1 = gelu_exact(v1); }
                    *(uint32_t*)&Cf[gi] = pack_f16_2(v0, v1);
                }
            }
        }
    }
}

// =====================================================================
// fp16 1-pass GEMM, 64x128 tile: bias + residual, f32 out.
// =====================================================================
__global__ __launch_bounds__(256, 2)
void gemm_g16(const __half* __restrict__ A, const __half* __restrict__ B,
              const float* __restrict__ bias, const float* __restrict__ res,
              float* __restrict__ C, int M, int N, int K)
{
    extern __shared__ char smem[];
    const uint32_t sb0 = smem_u32(smem);
    const int tid  = threadIdx.x;
    const int lane = tid & 31, wid = tid >> 5;
    const int m0 = blockIdx.y * 64, n0 = blockIdx.x * 128;
    const int wm = (wid >> 2) * 32, wn = (wid & 3) * 32;

    float acc[2][4][4];
    #pragma unroll
    for (int a = 0; a < 2; a++)
        #pragma unroll
        for (int b = 0; b < 4; b++)
            #pragma unroll
            for (int cc = 0; cc < 4; cc++) acc[a][b][cc] = 0.f;

    const int nch = K / KC;
    issue_stage_g16(A, B, sb0, tid, m0, n0, K, N, 0);
    issue_stage_g16(A, B, sb0, tid, m0, n0, K, N, 1);

    const uint32_t a_lrow = wm + (lane & 15);
    const uint32_t a_lcol = (lane >> 4) * 8;
    const uint32_t b_lrow = (lane & 15);

    for (int c = 0; c < nch; c++){
        asm volatile("cp.async.wait_group %0;" :: "n"(1));
        __syncthreads();
        if (c + 2 < nch) issue_stage_g16(A, B, sb0, tid, m0, n0, K, N, c + 2);
        else asm volatile("cp.async.commit_group;");

        uint32_t sb = sb0 + (uint32_t)(c % 3) * G_STAGE;
        #pragma unroll
        for (int ks = 0; ks < 4; ks++){
            uint32_t ah[2][4], bb[4][2];
            #pragma unroll
            for (int mt = 0; mt < 2; mt++)
                ldsm_x4(ah[mt], sb + (a_lrow + mt*16)*A_STRIDE + (ks*16 + a_lcol)*2);
            #pragma unroll
            for (int nt = 0; nt < 4; nt++)
                ldsm_x2t(bb[nt], sb + G_B_OFF + (ks*16 + b_lrow)*B_STRIDE + (wn + nt*8)*2);
            #pragma unroll
            for (int mt = 0; mt < 2; mt++)
                #pragma unroll
                for (int nt = 0; nt < 4; nt++)
                    mma_f16(acc[mt][nt], ah[mt], bb[nt]);
        }
    }

    const int g  = lane >> 2;
    const int tq = (lane & 3) * 2;
    #pragma unroll
    for (int mt = 0; mt < 2; mt++){
        #pragma unroll
        for (int half = 0; half < 2; half++){
            int m = m0 + wm + mt*16 + g + half*8;
            #pragma unroll
            for (int nt = 0; nt < 4; nt++){
                int n = n0 + wn + nt*8 + tq;
                float v0 = acc[mt][nt][half*2+0] + bias[n];
                float v1 = acc[mt][nt][half*2+1] + bias[n+1];
                size_t gi = (size_t)m * N + n;
                v0 += res[gi]; v1 += res[gi+1];
                float2 o; o.x = v0; o.y = v1;
                *(float2*)&C[gi] = o;
            }
        }
    }
}

// =====================================================================
// Flash attention, single fp16, causal. Balanced pairing (R14 config):
// Bq=64, 4 warps x 16 rows, CTA processes q-tiles (15-pair) then (pair)
// -> constant 17 KV-units per CTA. Softmax uses packed f16x2 ex2.
// smem: Q 0..9216 | stage s at 9216+s*18432: K +0, V +9216
// =====================================================================
#define FL_SMEM 46080

__global__ __launch_bounds__(128)
void flash_kernel(const __half* __restrict__ qkvf, __half* __restrict__ of)
{
    extern __shared__ char fsm[];
    const uint32_t sb = smem_u32(fsm);
    const int tid = threadIdx.x, lane = tid & 31, w = tid >> 5;   // w 0..3
    const int bh = blockIdx.x;
    const int pair = blockIdx.y;                                  // 0..7
    const int b = bh >> 4, h = bh & 15;
    const size_t rs = 3*DMODEL;
    const float L2E = 1.4426950408889634f;

    #define ISSUE_KV(jt_) do {                                               \
        uint32_t st_ = sb + 9216u + (uint32_t)((jt_)&1)*18432u;              \
        const size_t tok0_ = (size_t)(b*SEQ + (jt_)*64);                     \
        _Pragma("unroll")                                                    \
        for (int i_ = 0; i_ < 4; i_++){                                      \
            int idx_ = tid + i_*128;                                         \
            int r_ = idx_ >> 3, c_ = idx_ & 7;                               \
            uint32_t sa_ = st_ + r_*144 + c_*16;                             \
            cp16(sa_,        qkvf + (tok0_ + r_)*rs + DMODEL   + h*64 + c_*8); \
            cp16(sa_ + 9216, qkvf + (tok0_ + r_)*rs + 2*DMODEL + h*64 + c_*8); \
        }                                                                    \
        asm volatile("cp.async.commit_group;");                              \
    } while(0)

    #pragma unroll
    for (int hh = 0; hh < 2; hh++){
        const int it = hh ? pair : (15 - pair);   // heavy tile first
        const int nk = it + 1;

        // ---- Q loads (own group) ----
        {
            const size_t tok0 = (size_t)(b*SEQ + it*64);
            #pragma unroll
            for (int i = 0; i < 4; i++){
                int idx = tid + i*128;
                int r = idx >> 3, c = idx & 7;
                cp16(sb + r*144 + c*16, qkvf + (tok0 + r)*rs + h*64 + c*8);
            }
            asm volatile("cp.async.commit_group;");
        }
        ISSUE_KV(0);
        asm volatile("cp.async.wait_group 1;");   // Q ready
        __syncthreads();

        uint32_t qh[4][4];
        {
            uint32_t rbase = sb + (w*16 + (lane & 15))*144 + ((lane >> 4)*8)*2;
            #pragma unroll
            for (int ks = 0; ks < 4; ks++)
                ldsm_x4(qh[ks], rbase + ks*32);
        }

        float O[8][4];
        #pragma unroll
        for (int nt = 0; nt < 8; nt++)
            #pragma unroll
            for (int c = 0; c < 4; c++) O[nt][c] = 0.f;
        float m0 = -INFINITY, m1 = -INFINITY, l0 = 0.f, l1 = 0.f;
        const int r0g = it*64 + w*16 + (lane >> 2);

        for (int jt = 0; jt < nk; jt++){
            if (jt + 1 < nk){ ISSUE_KV(jt+1); asm volatile("cp.async.wait_group 1;"); }
            else            { asm volatile("cp.async.wait_group 0;"); }
            __syncthreads();
            const uint32_t st = sb + 9216u + (uint32_t)(jt&1)*18432u;

            float S[8][4];
            #pragma unroll
            for (int nt = 0; nt < 8; nt++)
                #pragma unroll
                for (int c = 0; c < 4; c++) S[nt][c] = 0.f;

            const uint32_t kb = st + (lane & 7)*144 + (((lane >> 3) & 1)*8)*2;
            #pragma unroll
            for (int nt = 0; nt < 8; nt++){
                #pragma unroll
                for (int ks = 0; ks < 4; ks++){
                    uint32_t kh[2];
                    ldsm_x2(kh, kb + nt*8*144 + ks*32);
                    mma_f16(S[nt], qh[ks], kh);
                }
            }

            const bool diag = (jt == it);
            float mx0 = -INFINITY, mx1 = -INFINITY;
            #pragma unroll
            for (int nt = 0; nt < 8; nt++){
                int colb = jt*64 + nt*8 + (lane & 3)*2;
                #pragma unroll
                for (int q = 0; q < 2; q++){
                    float v0 = S[nt][q]   * 0.125f;
                    float v1 = S[nt][2+q] * 0.125f;
                    if (diag){
                        if (colb + q > r0g)     v0 = -INFINITY;
                        if (colb + q > r0g + 8) v1 = -INFINITY;
                    }
                    S[nt][q] = v0; S[nt][2+q] = v1;
                    mx0 = fmaxf(mx0, v0); mx1 = fmaxf(mx1, v1);
                }
            }
            mx0 = fmaxf(mx0, __shfl_xor_sync(0xffffffffu, mx0, 1));
            mx0 = fmaxf(mx0, __shfl_xor_sync(0xffffffffu, mx0, 2));
            mx1 = fmaxf(mx1, __shfl_xor_sync(0xffffffffu, mx1, 1));
            mx1 = fmaxf(mx1, __shfl_xor_sync(0xffffffffu, mx1, 2));
            float mn0 = fmaxf(m0, mx0), mn1 = fmaxf(m1, mx1);
            float f0 = __expf(m0 - mn0), f1 = __expf(m1 - mn1);
            m0 = mn0; m1 = mn1;

            // packed-fp16 exp: P fragments produced directly
            uint32_t P0[8], P1[8];
            float ls0 = 0.f, ls1 = 0.f;
            #pragma unroll
            for (int nt = 0; nt < 8; nt++){
                uint32_t pa = pack_f16_2((S[nt][0]-m0)*L2E, (S[nt][1]-m0)*L2E);
                uint32_t pb = pack_f16_2((S[nt][2]-m1)*L2E, (S[nt][3]-m1)*L2E);
                pa = ex2_f16x2(pa);
                pb = ex2_f16x2(pb);
                P0[nt] = pa; P1[nt] = pb;
                float2 fa = __half22float2(*reinterpret_cast<__half2*>(&pa));
                float2 fb = __half22float2(*reinterpret_cast<__half2*>(&pb));
                ls0 += fa.x + fa.y;
                ls1 += fb.x + fb.y;
            }
            l0 = l0*f0 + ls0;
            l1 = l1*f1 + ls1;
            #pragma unroll
            for (int nt = 0; nt < 8; nt++){
                O[nt][0] *= f0; O[nt][1] *= f0;
                O[nt][2] *= f1; O[nt][3] *= f1;
            }

            #pragma unroll
            for (int ks = 0; ks < 4; ks++){
                uint32_t ph[4];
                ph[0] = P0[2*ks];
                ph[1] = P1[2*ks];
                ph[2] = P0[2*ks+1];
                ph[3] = P1[2*ks+1];
                uint32_t vb = st + 9216u + (ks*16 + (lane & 15))*144;
                #pragma unroll
                for (int nt = 0; nt < 8; nt++){
                    uint32_t vh[2];
                    ldsm_x2t(vh, vb + nt*16);
                    mma_f16(O[nt], ph, vh);
                }
            }
            __syncthreads();
        }

        l0 += __shfl_xor_sync(0xffffffffu, l0, 1);
        l0 += __shfl_xor_sync(0xffffffffu, l0, 2);
        l1 += __shfl_xor_sync(0xffffffffu, l1, 1);
        l1 += __shfl_xor_sync(0xffffffffu, l1, 2);
        float inv0 = 1.0f / l0, inv1 = 1.0f / l1;
        const size_t tok0 = (size_t)(b*SEQ + it*64 + w*16 + (lane >> 2));
        const int colb = h*64 + (lane & 3)*2;
        #pragma unroll
        for (int nt = 0; nt < 8; nt++){
            #pragma unroll
            for (int rh = 0; rh < 2; rh++){
                float inv = rh ? inv1 : inv0;
                float v0 = O[nt][rh*2+0] * inv;
                float v1 = O[nt][rh*2+1] * inv;
                size_t gi = (tok0 + rh*8)*DMODEL + colb + nt*8;
                *(uint32_t*)&of[gi] = pack_f16_2(v0, v1);
            }
        }
        __syncthreads();   // protect Q/KV buffers before the second tile
    }
    #undef ISSUE_KV
}

// ---------------- merged weight convert: fp32 -> fp16 (all 4 tensors) ----------------
__global__ void wconv_all_kernel(const float4* __restrict__ Wqkv,
                                 const float4* __restrict__ Wo,
                                 const float4* __restrict__ W1,
                                 const float4* __restrict__ W2,
                                 uint2* __restrict__ out){
    int i = blockIdx.x * blockDim.x + threadIdx.x;
    if (i >= WF_TOT/4) return;
    const float4* src;
    int off;
    if (i < WF_WO/4){ src = Wqkv; off = i; }
    else if (i < WF_W1/4){ src = Wo; off = i - WF_WO/4; }
    else if (i < WF_W2/4){ src = W1; off = i - WF_W1/4; }
    else { src = W2; off = i - WF_W2/4; }
    float4 v = src[off];
    uint2 o;
    o.x = pack_f16_2(v.x, v.y);
    o.y = pack_f16_2(v.z, v.w);
    out[i] = o;
}

// ---------------- LayerNorm: single fp16 out ----------------
__global__ void ln_kernel(const float* __restrict__ in,
                          const float* __restrict__ w,
                          const float* __restrict__ b,
                          __half* __restrict__ outf){
    int row = blockIdx.x;
    int t   = threadIdx.x;
    const float* x = in + (size_t)row * DMODEL;
    float4 v = *(const float4*)&x[t*4];
    float s  = v.x + v.y + v.z + v.w;
    float sq = v.x*v.x + v.y*v.y + v.z*v.z + v.w*v.w;
    s  = warp_sum(s);
    sq = warp_sum(sq);
    __shared__ float sh1[8], sh2[8];
    int warp = t >> 5, lane = t & 31;
    if (lane == 0){ sh1[warp] = s; sh2[warp] = sq; }
    __syncthreads();
    float tot = 0.f, tot2 = 0.f;
    #pragma unroll
    for (int i = 0; i < 8; i++){ tot += sh1[i]; tot2 += sh2[i]; }
    float mu   = tot  * (1.0f/DMODEL);
    float var  = tot2 * (1.0f/DMODEL) - mu*mu;
    float rstd = rsqrtf(var + EPS);
    float4 wv = *(const float4*)&w[t*4];
    float4 bv = *(const float4*)&b[t*4];
    float4 ov;
    ov.x = (v.x - mu)*rstd*wv.x + bv.x;
    ov.y = (v.y - mu)*rstd*wv.y + bv.y;
    ov.z = (v.z - mu)*rstd*wv.z + bv.z;
    ov.w = (v.w - mu)*rstd*wv.w + bv.w;
    size_t base = (size_t)row*DMODEL + t*4;
    uint2 H;
    H.x = pack_f16_2(ov.x, ov.y);
    H.y = pack_f16_2(ov.z, ov.w);
    *(uint2*)&outf[base] = H;
}

// ---------------- fused final LayerNorm + projection ----------------
__global__ __launch_bounds__(256)
void lnpred_kernel(const float* __restrict__ in,
                   const float* __restrict__ w,
                   const float* __restrict__ b,
                   const float* __restrict__ Wp,
                   const float* __restrict__ bp,
                   float* __restrict__ out){
    int row = blockIdx.x;
    int t   = threadIdx.x;
    const float* x = in + (size_t)row * DMODEL;
    float4 v = *(const float4*)&x[t*4];
    float s  = v.x + v.y + v.z + v.w;
    float sq = v.x*v.x + v.y*v.y + v.z*v.z + v.w*v.w;
    s  = warp_sum(s);
    sq = warp_sum(sq);
    __shared__ float sh1[8], sh2[8];
    int warp = t >> 5, lane = t & 31;
    if (lane == 0){ sh1[warp] = s; sh2[warp] = sq; }
    __syncthreads();
    float tot = 0.f, tot2 = 0.f;
    #pragma unroll
    for (int i = 0; i < 8; i++){ tot += sh1[i]; tot2 += sh2[i]; }
    float mu   = tot  * (1.0f/DMODEL);
    float var  = tot2 * (1.0f/DMODEL) - mu*mu;
    float rstd = rsqrtf(var + EPS);
    float4 wv = *(const float4*)&w[t*4];
    float4 bv = *(const float4*)&b[t*4];
    float4 ov;
    ov.x = (v.x - mu)*rstd*wv.x + bv.x;
    ov.y = (v.y - mu)*rstd*wv.y + bv.y;
    ov.z = (v.z - mu)*rstd*wv.z + bv.z;
    ov.w = (v.w - mu)*rstd*wv.w + bv.w;

    float local[WIN];
    {
        const float* w0 = Wp + (size_t)(t*4) * WIN;
        #pragma unroll
        for (int p = 0; p < WIN; p++)
            local[p] = ov.x*w0[p] + ov.y*w0[WIN+p] + ov.z*w0[2*WIN+p] + ov.w*w0[3*WIN+p];
    }
    __shared__ float red[WIN][256];
    #pragma unroll
    for (int p = 0; p < WIN; p++) red[p][t] = local[p];
    __syncthreads();
    for (int sHalf = 128; sHalf > 0; sHalf >>= 1){
        if (t < sHalf){
            #pragma unroll
            for (int p = 0; p < WIN; p++) red[p][t] += red[p][t + sHalf];
        }
        __syncthreads();
    }
    if (t < WIN) out[(size_t)row * WIN + t] = red[t][0] + bp[t];
}

// ---------------- host orchestration ----------------
extern "C" void kernel_launch(void* const* d_in, const int* in_sizes, int n_in,
                              void* d_out, int out_size){
    const float* x     = (const float*)d_in[0];
    const float* Wqkv  = (const float*)d_in[1];
    const float* bqkv  = (const float*)d_in[2];
    const float* Wo    = (const float*)d_in[3];
    const float* bo    = (const float*)d_in[4];
    const float* ln1w  = (const float*)d_in[5];
    const float* ln1b  = (const float*)d_in[6];
    const float* W1    = (const float*)d_in[7];
    const float* b1    = (const float*)d_in[8];
    const float* W2    = (const float*)d_in[9];
    const float* b2    = (const float*)d_in[10];
    const float* ln2w  = (const float*)d_in[11];
    const float* ln2b  = (const float*)d_in[12];
    const float* lnfw  = (const float*)d_in[13];
    const float* lnfb  = (const float*)d_in[14];
    const float* Wp    = (const float*)d_in[15];
    const float* bp    = (const float*)d_in[16];
    float* out = (float*)d_out;

    float *g_h;
    __half *g_hnf, *g_qkvf, *g_of, *g_fff, *g_wf16;
    cudaGetSymbolAddress((void**)&g_h,    d_h);
    cudaGetSymbolAddress((void**)&g_hnf,  d_hnf);
    cudaGetSymbolAddress((void**)&g_qkvf, d_qkvf);
    cudaGetSymbolAddress((void**)&g_of,   d_of);
    cudaGetSymbolAddress((void**)&g_fff,  d_fff);
    cudaGetSymbolAddress((void**)&g_wf16, d_wf16);

    cudaFuncSetAttribute(gemm_f16<0>, cudaFuncAttributeMaxDynamicSharedMemorySize, FGEMM_SMEM);
    cudaFuncSetAttribute(gemm_f16<2>, cudaFuncAttributeMaxDynamicSharedMemorySize, FGEMM_SMEM);
    cudaFuncSetAttribute(gemm_g16,    cudaFuncAttributeMaxDynamicSharedMemorySize, GGEMM_SMEM);
    cudaFuncSetAttribute(flash_kernel, cudaFuncAttributeMaxDynamicSharedMemorySize, FL_SMEM);

    wconv_all_kernel<<<(WF_TOT/4 + 255)/256, 256>>>(
        (const float4*)Wqkv, (const float4*)Wo, (const float4*)W1, (const float4*)W2,
        (uint2*)g_wf16);

    for (int l = 0; l < LAYERS; l++){
        const __half* wqkv = g_wf16 + WF_QKV + (size_t)l * DMODEL * 3*DMODEL;
        const __half* wo   = g_wf16 + WF_WO  + (size_t)l * DMODEL * DMODEL;
        const __half* w1   = g_wf16 + WF_W1  + (size_t)l * DMODEL * DFF;
        const __half* w2   = g_wf16 + WF_W2  + (size_t)l * DFF * DMODEL;
        const float* bq = bqkv + (size_t)l * 3*DMODEL;
        const float* bO = bo   + (size_t)l * DMODEL;
        const float* B1 = b1   + (size_t)l * DFF;
        const float* B2 = b2   + (size_t)l * DMODEL;
        const float* hin = (l == 0) ? x : g_h;

        // pre-norm attention
        ln_kernel<<<TOKENS, 256>>>(hin, ln1w + l*DMODEL, ln1b + l*DMODEL, g_hnf);
        gemm_f16<0><<<dim3(3*DMODEL/128, TOKENS/128), 256, FGEMM_SMEM>>>(
            g_hnf, wqkv, bq, nullptr, nullptr, g_qkvf, TOKENS, 3*DMODEL, DMODEL);
        flash_kernel<<<dim3(BATCH*NHEAD, 8), 128, FL_SMEM>>>(g_qkvf, g_of);
        gemm_g16<<<dim3(DMODEL/128, TOKENS/64), 256, GGEMM_SMEM>>>(
            g_of, wo, bO, hin, g_h, TOKENS, DMODEL, DMODEL);

        // pre-norm FFN
        ln_kernel<<<TOKENS, 256>>>(g_h, ln2w + l*DMODEL, ln2b + l*DMODEL, g_hnf);
        gemm_f16<2><<<dim3(DFF/128, TOKENS/128), 256, FGEMM_SMEM>>>(
            g_hnf, w1, B1, nullptr, nullptr, g_fff, TOKENS, DFF, DMODEL);
        gemm_g16<<<dim3(DMODEL/128, TOKENS/64), 256, GGEMM_SMEM>>>(
            g_fff, w2, B2, g_h, g_h, TOKENS, DMODEL, DFF);
    }

    lnpred_kernel<<<TOKENS, 256>>>(g_h, lnfw, lnfb, Wp, bp, out);
    (void)in_sizes; (void)n_in; (void)out_size;
}

// round 17
// speedup vs baseline: 1.0324x; 1.0076x over previous
#include <cuda_runtime.h>
#include <cuda_bf16.h>
#include <cuda_fp16.h>
#include <math.h>
#include <stdint.h>

// ---------------- problem constants ----------------
#define LAYERS 6
#define BATCH  2
#define SEQ    1024
#define DMODEL 1024
#define NHEAD  16
#define HDIM   64
#define DFF    4096
#define WIN    5
#define TOKENS (BATCH*SEQ)          // 2048
#define EPS    1e-5f

// fp16 weight scratch layout (elements)
#define QKV_ELEMS  (LAYERS*DMODEL*3*DMODEL)
#define WO_ELEMS   (LAYERS*DMODEL*DMODEL)
#define W1_ELEMS   (LAYERS*DMODEL*DFF)
#define W2_ELEMS   (LAYERS*DFF*DMODEL)
#define WF_QKV 0
#define WF_WO  (QKV_ELEMS)
#define WF_W1  (WF_WO + WO_ELEMS)
#define WF_W2  (WF_W1 + W1_ELEMS)
#define WF_TOT (WF_W2 + W2_ELEMS)

// ---------------- device scratch (no allocation allowed) ----------------
__device__ float d_h   [TOKENS*DMODEL];
__device__ __half d_hnf [TOKENS*DMODEL];
__device__ __half d_qkvf[TOKENS*3*DMODEL];
__device__ __half d_of  [TOKENS*DMODEL];
__device__ __half d_fff [TOKENS*DFF];
__device__ __half d_wf16[WF_TOT];

// ---------------- small helpers ----------------
__device__ __forceinline__ float warp_sum(float v){
    #pragma unroll
    for (int o = 16; o; o >>= 1) v += __shfl_xor_sync(0xffffffffu, v, o);
    return v;
}
__device__ __forceinline__ float gelu_exact(float x){
    return 0.5f * x * (1.0f + erff(x * 0.70710678118654752440f));
}
__device__ __forceinline__ uint32_t smem_u32(const void* p){
    uint32_t a;
    asm("{ .reg .u64 t; cvta.to.shared.u64 t, %1; cvt.u32.u64 %0, t; }" : "=r"(a) : "l"(p));
    return a;
}
__device__ __forceinline__ uint32_t pack_f16_2(float x, float y){
    __half2 h = __floats2half2_rn(x, y);
    return *reinterpret_cast<uint32_t*>(&h);
}

// ---------------- mma.sync / ldmatrix / cp.async wrappers ----------------
__device__ __forceinline__ void mma_f16(float* d, const uint32_t* a, const uint32_t* b){
    asm volatile(
      "mma.sync.aligned.m16n8k16.row.col.f32.f16.f16.f32 "
      "{%0,%1,%2,%3}, {%4,%5,%6,%7}, {%8,%9}, {%0,%1,%2,%3};\n"
      : "+f"(d[0]), "+f"(d[1]), "+f"(d[2]), "+f"(d[3])
      : "r"(a[0]), "r"(a[1]), "r"(a[2]), "r"(a[3]), "r"(b[0]), "r"(b[1]));
}
__device__ __forceinline__ void ldsm_x4(uint32_t* r, uint32_t addr){
    asm volatile("ldmatrix.sync.aligned.m8n8.x4.shared.b16 {%0,%1,%2,%3}, [%4];"
      : "=r"(r[0]), "=r"(r[1]), "=r"(r[2]), "=r"(r[3]) : "r"(addr));
}
__device__ __forceinline__ void ldsm_x2(uint32_t* r, uint32_t addr){
    asm volatile("ldmatrix.sync.aligned.m8n8.x2.shared.b16 {%0,%1}, [%2];"
      : "=r"(r[0]), "=r"(r[1]) : "r"(addr));
}
__device__ __forceinline__ void ldsm_x2t(uint32_t* r, uint32_t addr){
    asm volatile("ldmatrix.sync.aligned.m8n8.x2.trans.shared.b16 {%0,%1}, [%2];"
      : "=r"(r[0]), "=r"(r[1]) : "r"(addr));
}
__device__ __forceinline__ void cp16(uint32_t s, const void* g){
    asm volatile("cp.async.cg.shared.global [%0], [%1], 16;\n" :: "r"(s), "l"(g));
}
__device__ __forceinline__ uint32_t ex2_f16x2(uint32_t a){
    asm("ex2.approx.f16x2 %0, %0;" : "+r"(a));
    return a;
}

// ---------------- fp16 GEMM smem layouts (KC=64, 3 stages) ----------------
#define KC       64
#define A_STRIDE 144
#define B_STRIDE 272
// 128x128 tile
#define F_B_OFF  18432
#define F_STAGE  35840
#define FGEMM_SMEM (3*F_STAGE)
// 64x128 tile
#define G_B_OFF  9216
#define G_STAGE  26624
#define GGEMM_SMEM (3*G_STAGE)

__device__ __forceinline__ void issue_stage_f16(
    const __half* __restrict__ A, const __half* __restrict__ B,
    uint32_t sb0, int tid, int m0, int n0, int K, int N, int c)
{
    uint32_t sb = sb0 + (uint32_t)(c % 3) * F_STAGE;
    int k0 = c * KC;
    #pragma unroll
    for (int i = 0; i < 4; i++){
        int idx = tid + i*256;
        int r = idx >> 3, cc = idx & 7;
        cp16(sb + r*A_STRIDE + cc*16, A + (size_t)(m0 + r) * K + k0 + cc*8);
    }
    #pragma unroll
    for (int i = 0; i < 4; i++){
        int idx = tid + i*256;
        int r = idx >> 4, cc = idx & 15;
        cp16(sb + F_B_OFF + r*B_STRIDE + cc*16, B + (size_t)(k0 + r) * N + n0 + cc*8);
    }
    asm volatile("cp.async.commit_group;");
}

__device__ __forceinline__ void issue_stage_g16(
    const __half* __restrict__ A, const __half* __restrict__ B,
    uint32_t sb0, int tid, int m0, int n0, int K, int N, int c)
{
    uint32_t sb = sb0 + (uint32_t)(c % 3) * G_STAGE;
    int k0 = c * KC;
    #pragma unroll
    for (int i = 0; i < 2; i++){
        int idx = tid + i*256;
        int r = idx >> 3, cc = idx & 7;
        cp16(sb + r*A_STRIDE + cc*16, A + (size_t)(m0 + r) * K + k0 + cc*8);
    }
    #pragma unroll
    for (int i = 0; i < 4; i++){
        int idx = tid + i*256;
        int r = idx >> 4, cc = idx & 15;
        cp16(sb + G_B_OFF + r*B_STRIDE + cc*16, B + (size_t)(k0 + r) * N + n0 + cc*8);
    }
    asm volatile("cp.async.commit_group;");
}

// =====================================================================
// fp16 1-pass GEMM, 128x128 tile: C = epi(A @ B + bias)
// EPI: 0 = bias -> fp16   1 = bias+residual (f32)   2 = bias+GELU -> fp16
// =====================================================================
template<int EPI>
__global__ __launch_bounds__(256, 2)
void gemm_f16(const __half* __restrict__ A, const __half* __restrict__ B,
              const float* __restrict__ bias, const float* __restrict__ res,
              float* __restrict__ C, __half* __restrict__ Cf,
              int M, int N, int K)
{
    extern __shared__ char smem[];
    const uint32_t sb0 = smem_u32(smem);
    const int tid  = threadIdx.x;
    const int lane = tid & 31, wid = tid >> 5;
    const int m0 = blockIdx.y * 128, n0 = blockIdx.x * 128;
    const int wm = (wid >> 2) * 64, wn = (wid & 3) * 32;

    float acc[4][4][4];
    #pragma unroll
    for (int a = 0; a < 4; a++)
        #pragma unroll
        for (int b = 0; b < 4; b++)
            #pragma unroll
            for (int cc = 0; cc < 4; cc++) acc[a][b][cc] = 0.f;

    const int nch = K / KC;
    issue_stage_f16(A, B, sb0, tid, m0, n0, K, N, 0);
    issue_stage_f16(A, B, sb0, tid, m0, n0, K, N, 1);

    const uint32_t a_lrow = wm + (lane & 15);
    const uint32_t a_lcol = (lane >> 4) * 8;
    const uint32_t b_lrow = (lane & 15);

    for (int c = 0; c < nch; c++){
        asm volatile("cp.async.wait_group %0;" :: "n"(1));
        __syncthreads();
        if (c + 2 < nch) issue_stage_f16(A, B, sb0, tid, m0, n0, K, N, c + 2);
        else asm volatile("cp.async.commit_group;");

        uint32_t sb = sb0 + (uint32_t)(c % 3) * F_STAGE;
        #pragma unroll
        for (int ks = 0; ks < 4; ks++){
            uint32_t ah[4][4], bb[4][2];
            #pragma unroll
            for (int mt = 0; mt < 4; mt++)
                ldsm_x4(ah[mt], sb + (a_lrow + mt*16)*A_STRIDE + (ks*16 + a_lcol)*2);
            #pragma unroll
            for (int nt = 0; nt < 4; nt++)
                ldsm_x2t(bb[nt], sb + F_B_OFF + (ks*16 + b_lrow)*B_STRIDE + (wn + nt*8)*2);
            #pragma unroll
            for (int mt = 0; mt < 4; mt++)
                #pragma unroll
                for (int nt = 0; nt < 4; nt++)
                    mma_f16(acc[mt][nt], ah[mt], bb[nt]);
        }
    }

    const int g  = lane >> 2;
    const int tq = (lane & 3) * 2;
    #pragma unroll
    for (int mt = 0; mt < 4; mt++){
        #pragma unroll
        for (int half = 0; half < 2; half++){
            int m = m0 + wm + mt*16 + g + half*8;
            #pragma unroll
            for (int nt = 0; nt < 4; nt++){
                int n = n0 + wn + nt*8 + tq;
                float v0 = acc[mt][nt][half*2+0] + bias[n];
                float v1 = acc[mt][nt][half*2+1] + bias[n+1];
                size_t gi = (size_t)m * N + n;
                if (EPI == 1){
                    v0 += res[gi]; v1 += res[gi+1];
                    float2 o; o.x = v0; o.y = v1;
                    *(float2*)&C[gi] = o;
                } else {
                    if (EPI == 2){ v0 = gelu_exact(v0); v1 = gelu_exact(v1); }
                    *(uint32_t*)&Cf[gi] = pack_f16_2(v0, v1);
                }
            }
        }
    }
}

// =====================================================================
// fp16 1-pass GEMM, 64x128 tile: bias + residual, f32 out.
// =====================================================================
__global__ __launch_bounds__(256, 2)
void gemm_g16(const __half* __restrict__ A, const __half* __restrict__ B,
              const float* __restrict__ bias, const float* __restrict__ res,
              float* __restrict__ C, int M, int N, int K)
{
    extern __shared__ char smem[];
    const uint32_t sb0 = smem_u32(smem);
    const int tid  = threadIdx.x;
    const int lane = tid & 31, wid = tid >> 5;
    const int m0 = blockIdx.y * 64, n0 = blockIdx.x * 128;
    const int wm = (wid >> 2) * 32, wn = (wid & 3) * 32;

    float acc[2][4][4];
    #pragma unroll
    for (int a = 0; a < 2; a++)
        #pragma unroll
        for (int b = 0; b < 4; b++)
            #pragma unroll
            for (int cc = 0; cc < 4; cc++) acc[a][b][cc] = 0.f;

    const int nch = K / KC;
    issue_stage_g16(A, B, sb0, tid, m0, n0, K, N, 0);
    issue_stage_g16(A, B, sb0, tid, m0, n0, K, N, 1);

    const uint32_t a_lrow = wm + (lane & 15);
    const uint32_t a_lcol = (lane >> 4) * 8;
    const uint32_t b_lrow = (lane & 15);

    for (int c = 0; c < nch; c++){
        asm volatile("cp.async.wait_group %0;" :: "n"(1));
        __syncthreads();
        if (c + 2 < nch) issue_stage_g16(A, B, sb0, tid, m0, n0, K, N, c + 2);
        else asm volatile("cp.async.commit_group;");

        uint32_t sb = sb0 + (uint32_t)(c % 3) * G_STAGE;
        #pragma unroll
        for (int ks = 0; ks < 4; ks++){
            uint32_t ah[2][4], bb[4][2];
            #pragma unroll
            for (int mt = 0; mt < 2; mt++)
                ldsm_x4(ah[mt], sb + (a_lrow + mt*16)*A_STRIDE + (ks*16 + a_lcol)*2);
            #pragma unroll
            for (int nt = 0; nt < 4; nt++)
                ldsm_x2t(bb[nt], sb + G_B_OFF + (ks*16 + b_lrow)*B_STRIDE + (wn + nt*8)*2);
            #pragma unroll
            for (int mt = 0; mt < 2; mt++)
                #pragma unroll
                for (int nt = 0; nt < 4; nt++)
                    mma_f16(acc[mt][nt], ah[mt], bb[nt]);
        }
    }

    const int g  = lane >> 2;
    const int tq = (lane & 3) * 2;
    #pragma unroll
    for (int mt = 0; mt < 2; mt++){
        #pragma unroll
        for (int half = 0; half < 2; half++){
            int m = m0 + wm + mt*16 + g + half*8;
            #pragma unroll
            for (int nt = 0; nt < 4; nt++){
                int n = n0 + wn + nt*8 + tq;
                float v0 = acc[mt][nt][half*2+0] + bias[n];
                float v1 = acc[mt][nt][half*2+1] + bias[n+1];
                size_t gi = (size_t)m * N + n;
                v0 += res[gi]; v1 += res[gi+1];
                float2 o; o.x = v0; o.y = v1;
                *(float2*)&C[gi] = o;
            }
        }
    }
}

// =====================================================================
// Flash attention, single fp16, causal. Dual-group CTA:
// 256 threads = two independent 4-warp groups; group 0 -> tile (15-pair),
// group 1 -> tile (pair), each in its own 46KB smem region with its own
// named barrier (different trip counts). Softmax uses packed f16x2 ex2.
// Per-group smem: Q 0..9216 | stage s at 9216+s*18432: K +0, V +9216
// =====================================================================
#define FL_GRP_SMEM 46080
#define FL_SMEM     (2*FL_GRP_SMEM)   // 92160; 2 CTAs/SM

__global__ __launch_bounds__(256, 2)
void flash_kernel(const __half* __restrict__ qkvf, __half* __restrict__ of)
{
    extern __shared__ char fsm[];
    const int tid0 = threadIdx.x;
    const int grp  = tid0 >> 7;               // 0 or 1
    const int tid  = tid0 & 127;
    const int lane = tid & 31, w = tid >> 5;  // w 0..3 within group
    const uint32_t sb = smem_u32(fsm) + (uint32_t)grp * FL_GRP_SMEM;
    const int bh = blockIdx.x;
    const int pair = blockIdx.y;              // 0..7
    const int b = bh >> 4, h = bh & 15;
    const int it = grp ? pair : (15 - pair);
    const int nk = it + 1;
    const int barid = 1 + grp;
    const size_t rs = 3*DMODEL;
    const float L2E = 1.4426950408889634f;

    #define GSYNC() asm volatile("bar.sync %0, 128;" :: "r"(barid) : "memory")
    #define ISSUE_KV(jt_) do {                                               \
        uint32_t st_ = sb + 9216u + (uint32_t)((jt_)&1)*18432u;              \
        const size_t tok0_ = (size_t)(b*SEQ + (jt_)*64);                     \
        _Pragma("unroll")                                                    \
        for (int i_ = 0; i_ < 4; i_++){                                      \
            int idx_ = tid + i_*128;                                         \
            int r_ = idx_ >> 3, c_ = idx_ & 7;                               \
            uint32_t sa_ = st_ + r_*144 + c_*16;                             \
            cp16(sa_,        qkvf + (tok0_ + r_)*rs + DMODEL   + h*64 + c_*8); \
            cp16(sa_ + 9216, qkvf + (tok0_ + r_)*rs + 2*DMODEL + h*64 + c_*8); \
        }                                                                    \
        asm volatile("cp.async.commit_group;");                              \
    } while(0)

    // ---- Q loads (own group) ----
    {
        const size_t tok0 = (size_t)(b*SEQ + it*64);
        #pragma unroll
        for (int i = 0; i < 4; i++){
            int idx = tid + i*128;
            int r = idx >> 3, c = idx & 7;
            cp16(sb + r*144 + c*16, qkvf + (tok0 + r)*rs + h*64 + c*8);
        }
        asm volatile("cp.async.commit_group;");
    }
    ISSUE_KV(0);
    asm volatile("cp.async.wait_group 1;");   // Q ready
    GSYNC();

    uint32_t qh[4][4];
    {
        uint32_t rbase = sb + (w*16 + (lane & 15))*144 + ((lane >> 4)*8)*2;
        #pragma unroll
        for (int ks = 0; ks < 4; ks++)
            ldsm_x4(qh[ks], rbase + ks*32);
    }

    float O[8][4];
    #pragma unroll
    for (int nt = 0; nt < 8; nt++)
        #pragma unroll
        for (int c = 0; c < 4; c++) O[nt][c] = 0.f;
    float m0 = -INFINITY, m1 = -INFINITY, l0 = 0.f, l1 = 0.f;
    const int r0g = it*64 + w*16 + (lane >> 2);

    for (int jt = 0; jt < nk; jt++){
        if (jt + 1 < nk){ ISSUE_KV(jt+1); asm volatile("cp.async.wait_group 1;"); }
        else            { asm volatile("cp.async.wait_group 0;"); }
        GSYNC();
        const uint32_t st = sb + 9216u + (uint32_t)(jt&1)*18432u;

        float S[8][4];
        #pragma unroll
        for (int nt = 0; nt < 8; nt++)
            #pragma unroll
            for (int c = 0; c < 4; c++) S[nt][c] = 0.f;

        const uint32_t kb = st + (lane & 7)*144 + (((lane >> 3) & 1)*8)*2;
        #pragma unroll
        for (int nt = 0; nt < 8; nt++){
            #pragma unroll
            for (int ks = 0; ks < 4; ks++){
                uint32_t kh[2];
                ldsm_x2(kh, kb + nt*8*144 + ks*32);
                mma_f16(S[nt], qh[ks], kh);
            }
        }

        const bool diag = (jt == it);
        float mx0 = -INFINITY, mx1 = -INFINITY;
        #pragma unroll
        for (int nt = 0; nt < 8; nt++){
            int colb = jt*64 + nt*8 + (lane & 3)*2;
            #pragma unroll
            for (int q = 0; q < 2; q++){
                float v0 = S[nt][q]   * 0.125f;
                float v1 = S[nt][2+q] * 0.125f;
                if (diag){
                    if (colb + q > r0g)     v0 = -INFINITY;
                    if (colb + q > r0g + 8) v1 = -INFINITY;
                }
                S[nt][q] = v0; S[nt][2+q] = v1;
                mx0 = fmaxf(mx0, v0); mx1 = fmaxf(mx1, v1);
            }
        }
        mx0 = fmaxf(mx0, __shfl_xor_sync(0xffffffffu, mx0, 1));
        mx0 = fmaxf(mx0, __shfl_xor_sync(0xffffffffu, mx0, 2));
        mx1 = fmaxf(mx1, __shfl_xor_sync(0xffffffffu, mx1, 1));
        mx1 = fmaxf(mx1, __shfl_xor_sync(0xffffffffu, mx1, 2));
        float mn0 = fmaxf(m0, mx0), mn1 = fmaxf(m1, mx1);
        float f0 = __expf(m0 - mn0), f1 = __expf(m1 - mn1);
        m0 = mn0; m1 = mn1;

        uint32_t P0[8], P1[8];
        float ls0 = 0.f, ls1 = 0.f;
        #pragma unroll
        for (int nt = 0; nt < 8; nt++){
            uint32_t pa = pack_f16_2((S[nt][0]-m0)*L2E, (S[nt][1]-m0)*L2E);
            uint32_t pb = pack_f16_2((S[nt][2]-m1)*L2E, (S[nt][3]-m1)*L2E);
            pa = ex2_f16x2(pa);
            pb = ex2_f16x2(pb);
            P0[nt] = pa; P1[nt] = pb;
            float2 fa = __half22float2(*reinterpret_cast<__half2*>(&pa));
            float2 fb = __half22float2(*reinterpret_cast<__half2*>(&pb));
            ls0 += fa.x + fa.y;
            ls1 += fb.x + fb.y;
        }
        l0 = l0*f0 + ls0;
        l1 = l1*f1 + ls1;
        #pragma unroll
        for (int nt = 0; nt < 8; nt++){
            O[nt][0] *= f0; O[nt][1] *= f0;
            O[nt][2] *= f1; O[nt][3] *= f1;
        }

        #pragma unroll
        for (int ks = 0; ks < 4; ks++){
            uint32_t ph[4];
            ph[0] = P0[2*ks];
            ph[1] = P1[2*ks];
            ph[2] = P0[2*ks+1];
            ph[3] = P1[2*ks+1];
            uint32_t vb = st + 9216u + (ks*16 + (lane & 15))*144;
            #pragma unroll
            for (int nt = 0; nt < 8; nt++){
                uint32_t vh[2];
                ldsm_x2t(vh, vb + nt*16);
                mma_f16(O[nt], ph, vh);
            }
        }
        GSYNC();
    }

    l0 += __shfl_xor_sync(0xffffffffu, l0, 1);
    l0 += __shfl_xor_sync(0xffffffffu, l0, 2);
    l1 += __shfl_xor_sync(0xffffffffu, l1, 1);
    l1 += __shfl_xor_sync(0xffffffffu, l1, 2);
    float inv0 = 1.0f / l0, inv1 = 1.0f / l1;
    const size_t tok0 = (size_t)(b*SEQ + it*64 + w*16 + (lane >> 2));
    const int colb = h*64 + (lane & 3)*2;
    #pragma unroll
    for (int nt = 0; nt < 8; nt++){
        #pragma unroll
        for (int rh = 0; rh < 2; rh++){
            float inv = rh ? inv1 : inv0;
            float v0 = O[nt][rh*2+0] * inv;
            float v1 = O[nt][rh*2+1] * inv;
            size_t gi = (tok0 + rh*8)*DMODEL + colb + nt*8;
            *(uint32_t*)&of[gi] = pack_f16_2(v0, v1);
        }
    }
    #undef ISSUE_KV
    #undef GSYNC
}

// ---------------- merged weight convert: fp32 -> fp16 (all 4 tensors) ----------------
__global__ void wconv_all_kernel(const float4* __restrict__ Wqkv,
                                 const float4* __restrict__ Wo,
                                 const float4* __restrict__ W1,
                                 const float4* __restrict__ W2,
                                 uint2* __restrict__ out){
    int i = blockIdx.x * blockDim.x + threadIdx.x;
    if (i >= WF_TOT/4) return;
    const float4* src;
    int off;
    if (i < WF_WO/4){ src = Wqkv; off = i; }
    else if (i < WF_W1/4){ src = Wo; off = i - WF_WO/4; }
    else if (i < WF_W2/4){ src = W1; off = i - WF_W1/4; }
    else { src = W2; off = i - WF_W2/4; }
    float4 v = src[off];
    uint2 o;
    o.x = pack_f16_2(v.x, v.y);
    o.y = pack_f16_2(v.z, v.w);
    out[i] = o;
}

// ---------------- LayerNorm: single fp16 out ----------------
__global__ void ln_kernel(const float* __restrict__ in,
                          const float* __restrict__ w,
                          const float* __restrict__ b,
                          __half* __restrict__ outf){
    int row = blockIdx.x;
    int t   = threadIdx.x;
    const float* x = in + (size_t)row * DMODEL;
    float4 v = *(const float4*)&x[t*4];
    float s  = v.x + v.y + v.z + v.w;
    float sq = v.x*v.x + v.y*v.y + v.z*v.z + v.w*v.w;
    s  = warp_sum(s);
    sq = warp_sum(sq);
    __shared__ float sh1[8], sh2[8];
    int warp = t >> 5, lane = t & 31;
    if (lane == 0){ sh1[warp] = s; sh2[warp] = sq; }
    __syncthreads();
    float tot = 0.f, tot2 = 0.f;
    #pragma unroll
    for (int i = 0; i < 8; i++){ tot += sh1[i]; tot2 += sh2[i]; }
    float mu   = tot  * (1.0f/DMODEL);
    float var  = tot2 * (1.0f/DMODEL) - mu*mu;
    float rstd = rsqrtf(var + EPS);
    float4 wv = *(const float4*)&w[t*4];
    float4 bv = *(const float4*)&b[t*4];
    float4 ov;
    ov.x = (v.x - mu)*rstd*wv.x + bv.x;
    ov.y = (v.y - mu)*rstd*wv.y + bv.y;
    ov.z = (v.z - mu)*rstd*wv.z + bv.z;
    ov.w = (v.w - mu)*rstd*wv.w + bv.w;
    size_t base = (size_t)row*DMODEL + t*4;
    uint2 H;
    H.x = pack_f16_2(ov.x, ov.y);
    H.y = pack_f16_2(ov.z, ov.w);
    *(uint2*)&outf[base] = H;
}

// ---------------- fused final LayerNorm + projection ----------------
__global__ __launch_bounds__(256)
void lnpred_kernel(const float* __restrict__ in,
                   const float* __restrict__ w,
                   const float* __restrict__ b,
                   const float* __restrict__ Wp,
                   const float* __restrict__ bp,
                   float* __restrict__ out){
    int row = blockIdx.x;
    int t   = threadIdx.x;
    const float* x = in + (size_t)row * DMODEL;
    float4 v = *(const float4*)&x[t*4];
    float s  = v.x + v.y + v.z + v.w;
    float sq = v.x*v.x + v.y*v.y + v.z*v.z + v.w*v.w;
    s  = warp_sum(s);
    sq = warp_sum(sq);
    __shared__ float sh1[8], sh2[8];
    int warp = t >> 5, lane = t & 31;
    if (lane == 0){ sh1[warp] = s; sh2[warp] = sq; }
    __syncthreads();
    float tot = 0.f, tot2 = 0.f;
    #pragma unroll
    for (int i = 0; i < 8; i++){ tot += sh1[i]; tot2 += sh2[i]; }
    float mu   = tot  * (1.0f/DMODEL);
    float var  = tot2 * (1.0f/DMODEL) - mu*mu;
    float rstd = rsqrtf(var + EPS);
    float4 wv = *(const float4*)&w[t*4];
    float4 bv = *(const float4*)&b[t*4];
    float4 ov;
    ov.x = (v.x - mu)*rstd*wv.x + bv.x;
    ov.y = (v.y - mu)*rstd*wv.y + bv.y;
    ov.z = (v.z - mu)*rstd*wv.z + bv.z;
    ov.w = (v.w - mu)*rstd*wv.w + bv.w;

    float local[WIN];
    {
        const float* w0 = Wp + (size_t)(t*4) * WIN;
        #pragma unroll
        for (int p = 0; p < WIN; p++)
            local[p] = ov.x*w0[p] + ov.y*w0[WIN+p] + ov.z*w0[2*WIN+p] + ov.w*w0[3*WIN+p];
    }
    __shared__ float red[WIN][256];
    #pragma unroll
    for (int p = 0; p < WIN; p++) red[p][t] = local[p];
    __syncthreads();
    for (int sHalf = 128; sHalf > 0; sHalf >>= 1){
        if (t < sHalf){
            #pragma unroll
            for (int p = 0; p < WIN; p++) red[p][t] += red[p][t + sHalf];
        }
        __syncthreads();
    }
    if (t < WIN) out[(size_t)row * WIN + t] = red[t][0] + bp[t];
}

// ---------------- host orchestration ----------------
extern "C" void kernel_launch(void* const* d_in, const int* in_sizes, int n_in,
                              void* d_out, int out_size){
    const float* x     = (const float*)d_in[0];
    const float* Wqkv  = (const float*)d_in[1];
    const float* bqkv  = (const float*)d_in[2];
    const float* Wo    = (const float*)d_in[3];
    const float* bo    = (const float*)d_in[4];
    const float* ln1w  = (const float*)d_in[5];
    const float* ln1b  = (const float*)d_in[6];
    const float* W1    = (const float*)d_in[7];
    const float* b1    = (const float*)d_in[8];
    const float* W2    = (const float*)d_in[9];
    const float* b2    = (const float*)d_in[10];
    const float* ln2w  = (const float*)d_in[11];
    const float* ln2b  = (const float*)d_in[12];
    const float* lnfw  = (const float*)d_in[13];
    const float* lnfb  = (const float*)d_in[14];
    const float* Wp    = (const float*)d_in[15];
    const float* bp    = (const float*)d_in[16];
    float* out = (float*)d_out;

    float *g_h;
    __half *g_hnf, *g_qkvf, *g_of, *g_fff, *g_wf16;
    cudaGetSymbolAddress((void**)&g_h,    d_h);
    cudaGetSymbolAddress((void**)&g_hnf,  d_hnf);
    cudaGetSymbolAddress((void**)&g_qkvf, d_qkvf);
    cudaGetSymbolAddress((void**)&g_of,   d_of);
    cudaGetSymbolAddress((void**)&g_fff,  d_fff);
    cudaGetSymbolAddress((void**)&g_wf16, d_wf16);

    cudaFuncSetAttribute(gemm_f16<0>, cudaFuncAttributeMaxDynamicSharedMemorySize, FGEMM_SMEM);
    cudaFuncSetAttribute(gemm_f16<2>, cudaFuncAttributeMaxDynamicSharedMemorySize, FGEMM_SMEM);
    cudaFuncSetAttribute(gemm_g16,    cudaFuncAttributeMaxDynamicSharedMemorySize, GGEMM_SMEM);
    cudaFuncSetAttribute(flash_kernel, cudaFuncAttributeMaxDynamicSharedMemorySize, FL_SMEM);

    wconv_all_kernel<<<(WF_TOT/4 + 255)/256, 256>>>(
        (const float4*)Wqkv, (const float4*)Wo, (const float4*)W1, (const float4*)W2,
        (uint2*)g_wf16);

    for (int l = 0; l < LAYERS; l++){
        const __half* wqkv = g_wf16 + WF_QKV + (size_t)l * DMODEL * 3*DMODEL;
        const __half* wo   = g_wf16 + WF_WO  + (size_t)l * DMODEL * DMODEL;
        const __half* w1   = g_wf16 + WF_W1  + (size_t)l * DMODEL * DFF;
        const __half* w2   = g_wf16 + WF_W2  + (size_t)l * DFF * DMODEL;
        const float* bq = bqkv + (size_t)l * 3*DMODEL;
        const float* bO = bo   + (size_t)l * DMODEL;
        const float* B1 = b1   + (size_t)l * DFF;
        const float* B2 = b2   + (size_t)l * DMODEL;
        const float* hin = (l == 0) ? x : g_h;

        // pre-norm attention
        ln_kernel<<<TOKENS, 256>>>(hin, ln1w + l*DMODEL, ln1b + l*DMODEL, g_hnf);
        gemm_f16<0><<<dim3(3*DMODEL/128, TOKENS/128), 256, FGEMM_SMEM>>>(
            g_hnf, wqkv, bq, nullptr, nullptr, g_qkvf, TOKENS, 3*DMODEL, DMODEL);
        flash_kernel<<<dim3(BATCH*NHEAD, 8), 256, FL_SMEM>>>(g_qkvf, g_of);
        gemm_g16<<<dim3(DMODEL/128, TOKENS/64), 256, GGEMM_SMEM>>>(
            g_of, wo, bO, hin, g_h, TOKENS, DMODEL, DMODEL);

        // pre-norm FFN
        ln_kernel<<<TOKENS, 256>>>(g_h, ln2w + l*DMODEL, ln2b + l*DMODEL, g_hnf);
        gemm_f16<2><<<dim3(DFF/128, TOKENS/128), 256, FGEMM_SMEM>>>(
            g_hnf, w1, B1, nullptr, nullptr, g_fff, TOKENS, DFF, DMODEL);
        gemm_g16<<<dim3(DMODEL/128, TOKENS/64), 256, GGEMM_SMEM>>>(
            g_fff, w2, B2, g_h, g_h, TOKENS, DMODEL, DFF);
    }

    lnpred_kernel<<<TOKENS, 256>>>(g_h, lnfw, lnfb, Wp, bp, out);
    (void)in_sizes; (void)n_in; (void)out_size;
}